// round 3
// baseline (speedup 1.0000x reference)
#include <cuda_runtime.h>
#include <math.h>

// Problem constants (fixed by the dataset)
#define BATCH   16384
#define NMOD    256
#define NGENE   50
#define NHID    8
#define NCOMP   70

// Kernel 1 tiling
#define BT1     512          // batches per block
#define T1      256          // threads
#define XS      51           // smem row stride (odd -> conflict-free)

// Kernel 2 tiling
#define BT2     64
#define T2      256
#define MS      257          // smem row stride for m tile

// ---------------------------------------------------------------------------
// Kernel 1: per-module 2-layer MLP with tanhshrink.
//   h[b,m,:]  = tanhshrink(x[b, m*50 : m*50+50] @ W1[m])      (G=50 -> H=8)
//   mval[b,m] = tanhshrink(h . W2[m] + b2[m])
// Grid: (NMOD, BATCH/BT1). Each thread computes 2 batches (t and t+256).
// ---------------------------------------------------------------------------
__global__ __launch_bounds__(T1, 2)
void flux_mod_kernel(const float* __restrict__ x,
                     const float* __restrict__ W1,
                     const float* __restrict__ W2,
                     const float* __restrict__ b2,
                     float* __restrict__ out_m)
{
    __shared__ float W1s[NGENE * NHID];   // [g*8 + j]
    __shared__ float W2s[NHID];
    __shared__ float b2s;
    extern __shared__ float sx[];         // [BT1][XS]

    const int m = blockIdx.x;
    const int bt = blockIdx.y;
    const int t = threadIdx.x;

    // weights for this module
    for (int i = t; i < NGENE * NHID; i += T1)
        W1s[i] = W1[(size_t)m * (NGENE * NHID) + i];
    if (t < NHID) W2s[t] = W2[m * NHID + t];
    if (t == 0)   b2s = b2[m];

    // Stage x tile: 512 rows x 50 floats (200B contiguous per row, 8B aligned)
    const float* xblk = x + (size_t)(bt * BT1) * (NMOD * NGENE) + (size_t)m * NGENE;
    for (int i = t; i < BT1 * 25; i += T1) {
        int b = i / 25;
        int j = i - b * 25;
        float2 v = *reinterpret_cast<const float2*>(xblk + (size_t)b * (NMOD * NGENE) + 2 * j);
        sx[b * XS + 2 * j]     = v.x;
        sx[b * XS + 2 * j + 1] = v.y;
    }
    __syncthreads();

    float h0[NHID], h1[NHID];
    #pragma unroll
    for (int j = 0; j < NHID; j++) { h0[j] = 0.f; h1[j] = 0.f; }

    const float* r0 = &sx[t * XS];             // bank-conflict-free (19t mod 32)
    const float* r1 = &sx[(t + 256) * XS];     // +256*51 = 0 mod 32, also clean

    #pragma unroll 5
    for (int g = 0; g < NGENE; g++) {
        float a0 = r0[g];
        float a1 = r1[g];
        #pragma unroll
        for (int j = 0; j < NHID; j++) {
            float w = W1s[g * NHID + j];       // warp-uniform broadcast
            h0[j] = fmaf(a0, w, h0[j]);
            h1[j] = fmaf(a1, w, h1[j]);
        }
    }

    float acc0 = b2s, acc1 = b2s;
    #pragma unroll
    for (int j = 0; j < NHID; j++) {
        float w  = W2s[j];
        float t0 = h0[j] - tanhf(h0[j]);
        float t1 = h1[j] - tanhf(h1[j]);
        acc0 = fmaf(t0, w, acc0);
        acc1 = fmaf(t1, w, acc1);
    }
    acc0 = acc0 - tanhf(acc0);
    acc1 = acc1 - tanhf(acc1);

    const size_t b0 = (size_t)bt * BT1 + t;
    out_m[b0 * NMOD + m]         = acc0;   // column writes; L2 merges across
    out_m[(b0 + 256) * NMOD + m] = acc1;   // the concurrent m-blocks
}

// ---------------------------------------------------------------------------
// Kernel 2: c = m @ cmMat^T   ([B,256] x [70,256]^T -> [B,70])
// Grid: BATCH/BT2 blocks. cmMat + m-tile staged in smem.
// Thread: batch lane b0 = t&31 (and b0+32), comp group cg = t>>5 (step 8).
// ---------------------------------------------------------------------------
__global__ __launch_bounds__(T2, 1)
void flux_comp_kernel(const float* __restrict__ mvals,
                      const float* __restrict__ cmMat,
                      float* __restrict__ out_c)
{
    extern __shared__ float sh[];
    float* scm = sh;                       // [70][256]
    float* sm  = sh + NCOMP * NMOD;        // [64][MS]

    const int t = threadIdx.x;
    const int bblk = blockIdx.x;

    for (int i = t; i < NCOMP * NMOD; i += T2)
        scm[i] = cmMat[i];

    const float* mblk = mvals + (size_t)bblk * BT2 * NMOD;
    for (int i = t; i < BT2 * NMOD; i += T2) {
        int b = i >> 8;
        int k = i & 255;
        sm[b * MS + k] = mblk[i];
    }
    __syncthreads();

    const int b0 = t & 31;
    const int cg = t >> 5;
    const float* r0 = &sm[b0 * MS];          // stride 257 -> conflict-free
    const float* r1 = &sm[(b0 + 32) * MS];
    const size_t gb0 = (size_t)bblk * BT2 + b0;

    for (int cc = cg; cc < NCOMP; cc += 8) {
        const float* crow = &scm[cc * NMOD]; // warp-uniform broadcast
        float a0 = 0.f, a1 = 0.f;
        #pragma unroll 8
        for (int k = 0; k < NMOD; k++) {
            float cv = crow[k];
            a0 = fmaf(r0[k], cv, a0);
            a1 = fmaf(r1[k], cv, a1);
        }
        out_c[gb0 * NCOMP + cc]        = a0;
        out_c[(gb0 + 32) * NCOMP + cc] = a1;
    }
}

// ---------------------------------------------------------------------------
extern "C" void kernel_launch(void* const* d_in, const int* in_sizes, int n_in,
                              void* d_out, int out_size)
{
    const float* x     = (const float*)d_in[0];  // [B, M*G]
    const float* W1    = (const float*)d_in[1];  // [M, G, H]
    const float* W2    = (const float*)d_in[2];  // [M, H]
    const float* b2    = (const float*)d_in[3];  // [M]
    const float* cmMat = (const float*)d_in[4];  // [C, M]
    (void)in_sizes; (void)n_in; (void)out_size;

    float* out   = (float*)d_out;
    float* out_m = out;                            // [B, M]
    float* out_c = out + (size_t)BATCH * NMOD;     // [B, C]

    const int smem1 = BT1 * XS * sizeof(float);                    // 104448 B
    const int smem2 = (NCOMP * NMOD + BT2 * MS) * sizeof(float);   // 137472 B
    cudaFuncSetAttribute(flux_mod_kernel,
                         cudaFuncAttributeMaxDynamicSharedMemorySize, smem1);
    cudaFuncSetAttribute(flux_comp_kernel,
                         cudaFuncAttributeMaxDynamicSharedMemorySize, smem2);

    dim3 grid1(NMOD, BATCH / BT1);   // m is fast dim -> concurrent m-blocks
    flux_mod_kernel<<<grid1, T1, smem1>>>(x, W1, W2, b2, out_m);

    flux_comp_kernel<<<BATCH / BT2, T2, smem2>>>(out_m, cmMat, out_c);
}

// round 5
// speedup vs baseline: 1.0985x; 1.0985x over previous
#include <cuda_runtime.h>
#include <math.h>

// Problem constants (fixed by the dataset)
#define BATCH   16384
#define NMOD    256
#define NGENE   50
#define NHID    8
#define NCOMP   70

// Kernel 1: BT1 batches per block, 8 warps, each warp owns 64 batches.
#define BT1     512
#define T1      256
#define XS      50           // smem row stride; gcd-safe for LDS.64 half-warp access

// Kernel 2
#define BT2     32
#define T2      256
#define CPAD    72           // cmMat padded comps (multiple of 8)
#define MS2     33           // m-tile row stride (odd -> conflict-free)

// Scratch: m transposed [M][B] so kernel1 writes and kernel2 reads are coalesced.
__device__ float g_mT[(size_t)NMOD * BATCH];

// ---------------------------------------------------------------------------
// Kernel 1: per-module 2-layer MLP with tanhshrink. Writes m_T[m][b] only.
// Grid: (NMOD, BATCH/BT1). Warp-autonomous: after a single weights sync, each
// warp stages its own 64-row x slab and computes (load/compute overlap across
// 16 warps/SM keeps HBM busy).
// ---------------------------------------------------------------------------
__global__ __launch_bounds__(T1, 2)
void flux_mod_kernel(const float* __restrict__ x,
                     const float* __restrict__ W1,
                     const float* __restrict__ W2,
                     const float* __restrict__ b2)
{
    __shared__ float W1s[NGENE * NHID];   // [g*8 + j]
    __shared__ float W2s[NHID];
    __shared__ float b2s_;
    extern __shared__ float sx[];         // [BT1][XS]

    const int m    = blockIdx.x;
    const int bt   = blockIdx.y;
    const int t    = threadIdx.x;
    const int warp = t >> 5;
    const int lane = t & 31;

    // Stage this module's weights (only block-wide sync in the kernel)
    for (int i = t; i < NGENE * NHID; i += T1)
        W1s[i] = W1[(size_t)m * (NGENE * NHID) + i];
    if (t < NHID) W2s[t] = W2[m * NHID + t];
    if (t == 0)   b2s_ = b2[m];
    __syncthreads();

    // Warp stages its own 64 rows (200B each, float2 per lane<25)
    const int rbase = warp * 64;
    const float* xw = x + (size_t)(bt * BT1 + rbase) * (NMOD * NGENE)
                        + (size_t)m * NGENE;
    float* sxw = sx + rbase * XS;
    if (lane < 25) {
        const float2* src = reinterpret_cast<const float2*>(xw) + lane;
        #pragma unroll 4
        for (int r = 0; r < 64; r++) {
            float2 v = *src;
            *reinterpret_cast<float2*>(sxw + r * XS + 2 * lane) = v;
            src += (NMOD * NGENE) / 2;
        }
    }
    __syncwarp();

    // Compute: lane handles batches (rbase+lane) and (rbase+lane+32)
    const float* __restrict__ r0 = sx + (rbase + lane) * XS;
    const float* __restrict__ r1 = r0 + 32 * XS;

    float h0[NHID], h1[NHID];
    #pragma unroll
    for (int j = 0; j < NHID; j++) { h0[j] = 0.f; h1[j] = 0.f; }

    #pragma unroll 5
    for (int gp = 0; gp < NGENE / 2; gp++) {
        const int g = gp * 2;
        float2 a0 = *reinterpret_cast<const float2*>(r0 + g);   // LDS.64, conflict-free
        float2 a1 = *reinterpret_cast<const float2*>(r1 + g);
        float4 wa = *reinterpret_cast<const float4*>(W1s + g * 8);       // uniform broadcast
        float4 wb = *reinterpret_cast<const float4*>(W1s + g * 8 + 4);
        float4 wc = *reinterpret_cast<const float4*>(W1s + g * 8 + 8);
        float4 wd = *reinterpret_cast<const float4*>(W1s + g * 8 + 12);

        h0[0] = fmaf(a0.x, wa.x, h0[0]); h0[1] = fmaf(a0.x, wa.y, h0[1]);
        h0[2] = fmaf(a0.x, wa.z, h0[2]); h0[3] = fmaf(a0.x, wa.w, h0[3]);
        h0[4] = fmaf(a0.x, wb.x, h0[4]); h0[5] = fmaf(a0.x, wb.y, h0[5]);
        h0[6] = fmaf(a0.x, wb.z, h0[6]); h0[7] = fmaf(a0.x, wb.w, h0[7]);
        h0[0] = fmaf(a0.y, wc.x, h0[0]); h0[1] = fmaf(a0.y, wc.y, h0[1]);
        h0[2] = fmaf(a0.y, wc.z, h0[2]); h0[3] = fmaf(a0.y, wc.w, h0[3]);
        h0[4] = fmaf(a0.y, wd.x, h0[4]); h0[5] = fmaf(a0.y, wd.y, h0[5]);
        h0[6] = fmaf(a0.y, wd.z, h0[6]); h0[7] = fmaf(a0.y, wd.w, h0[7]);

        h1[0] = fmaf(a1.x, wa.x, h1[0]); h1[1] = fmaf(a1.x, wa.y, h1[1]);
        h1[2] = fmaf(a1.x, wa.z, h1[2]); h1[3] = fmaf(a1.x, wa.w, h1[3]);
        h1[4] = fmaf(a1.x, wb.x, h1[4]); h1[5] = fmaf(a1.x, wb.y, h1[5]);
        h1[6] = fmaf(a1.x, wb.z, h1[6]); h1[7] = fmaf(a1.x, wb.w, h1[7]);
        h1[0] = fmaf(a1.y, wc.x, h1[0]); h1[1] = fmaf(a1.y, wc.y, h1[1]);
        h1[2] = fmaf(a1.y, wc.z, h1[2]); h1[3] = fmaf(a1.y, wc.w, h1[3]);
        h1[4] = fmaf(a1.y, wd.x, h1[4]); h1[5] = fmaf(a1.y, wd.y, h1[5]);
        h1[6] = fmaf(a1.y, wd.z, h1[6]); h1[7] = fmaf(a1.y, wd.w, h1[7]);
    }

    float acc0 = b2s_, acc1 = b2s_;
    #pragma unroll
    for (int j = 0; j < NHID; j++) {
        float w = W2s[j];
        acc0 = fmaf(h0[j] - tanhf(h0[j]), w, acc0);
        acc1 = fmaf(h1[j] - tanhf(h1[j]), w, acc1);
    }
    acc0 = acc0 - tanhf(acc0);
    acc1 = acc1 - tanhf(acc1);

    const size_t b = (size_t)bt * BT1 + rbase + lane;
    g_mT[(size_t)m * BATCH + b]      = acc0;   // fully coalesced writes
    g_mT[(size_t)m * BATCH + b + 32] = acc1;
}

// ---------------------------------------------------------------------------
// Kernel 2: emit out_m (coalesced, from m_T via smem transpose) and
//           out_c = m @ cmMat^T.
// Grid: BATCH/BT2 = 512 blocks. smem: cmMat padded [72][256] + m-tile [256][33].
// ---------------------------------------------------------------------------
__global__ __launch_bounds__(T2, 2)
void flux_comp_kernel(const float* __restrict__ cmMat,
                      float* __restrict__ out_m,
                      float* __restrict__ out_c)
{
    extern __shared__ float sh[];
    float* scm = sh;                        // [CPAD][256]
    float* sm  = sh + CPAD * NMOD;          // [256][MS2]

    const int t  = threadIdx.x;
    const int bb = blockIdx.x;
    const size_t bbase = (size_t)bb * BT2;

    for (int i = t; i < NCOMP * NMOD; i += T2) scm[i] = cmMat[i];
    for (int i = t; i < (CPAD - NCOMP) * NMOD; i += T2) scm[NCOMP * NMOD + i] = 0.f;

    for (int i = t; i < BT2 * NMOD; i += T2) {
        int k = i >> 5, b = i & 31;
        sm[k * MS2 + b] = g_mT[(size_t)k * BATCH + bbase + b];   // coalesced read
    }
    __syncthreads();

    // Emit out_m: read smem (conflict-free), write coalesced over k
    for (int i = t; i < BT2 * NMOD; i += T2) {
        int b = i >> 8, k = i & 255;
        out_m[(bbase + b) * NMOD + k] = sm[k * MS2 + b];
    }

    // c: lane b0 = t&31, comp group cg = t>>5 (9 comps each over padded 72)
    const int b0 = t & 31;
    const int cg = t >> 5;
    float acc[9];
    #pragma unroll
    for (int i = 0; i < 9; i++) acc[i] = 0.f;

    for (int k = 0; k < NMOD; k += 4) {
        float mv0 = sm[(k + 0) * MS2 + b0];
        float mv1 = sm[(k + 1) * MS2 + b0];
        float mv2 = sm[(k + 2) * MS2 + b0];
        float mv3 = sm[(k + 3) * MS2 + b0];
        #pragma unroll
        for (int idx = 0; idx < 9; idx++) {
            const int cc = cg + idx * 8;
            float4 cv = *reinterpret_cast<const float4*>(scm + cc * NMOD + k);
            acc[idx] = fmaf(mv0, cv.x,
                       fmaf(mv1, cv.y,
                       fmaf(mv2, cv.z,
                       fmaf(mv3, cv.w, acc[idx]))));
        }
    }

    const size_t gb = bbase + b0;
    #pragma unroll
    for (int idx = 0; idx < 9; idx++) {
        const int cc = cg + idx * 8;
        if (cc < NCOMP)
            out_c[gb * NCOMP + cc] = acc[idx];
    }
}

// ---------------------------------------------------------------------------
extern "C" void kernel_launch(void* const* d_in, const int* in_sizes, int n_in,
                              void* d_out, int out_size)
{
    const float* x     = (const float*)d_in[0];  // [B, M*G]
    const float* W1    = (const float*)d_in[1];  // [M, G, H]
    const float* W2    = (const float*)d_in[2];  // [M, H]
    const float* b2    = (const float*)d_in[3];  // [M]
    const float* cmMat = (const float*)d_in[4];  // [C, M]
    (void)in_sizes; (void)n_in; (void)out_size;

    float* out   = (float*)d_out;
    float* out_m = out;                            // [B, M]
    float* out_c = out + (size_t)BATCH * NMOD;     // [B, C]

    const int smem1 = BT1 * XS * sizeof(float);                     // 102400 B
    const int smem2 = (CPAD * NMOD + NMOD * MS2) * sizeof(float);   // 107520 B
    cudaFuncSetAttribute(flux_mod_kernel,
                         cudaFuncAttributeMaxDynamicSharedMemorySize, smem1);
    cudaFuncSetAttribute(flux_comp_kernel,
                         cudaFuncAttributeMaxDynamicSharedMemorySize, smem2);

    dim3 grid1(NMOD, BATCH / BT1);
    flux_mod_kernel<<<grid1, T1, smem1>>>(x, W1, W2, b2);

    flux_comp_kernel<<<BATCH / BT2, T2, smem2>>>(cmMat, out_m, out_c);
}